// round 16
// baseline (speedup 1.0000x reference)
#include <cuda_runtime.h>
#include <cuda_bf16.h>
#include <cstdint>

#define NX   8192
#define NN   8192
#define DIN  512
#define DH   32
#define DOUT 256
#define NSPLIT 4

// ---------------- scratch (static __device__: allocation-free) ----------------
__device__ __nv_bfloat16 g_xattb[NX * DH];              // bf16 att (x)
__device__ __nv_bfloat16 g_nattb[NN * DH];              // bf16 att (neigh)
__device__ __nv_bfloat16 g_valueT[(size_t)DOUT * NN];   // 4 MB, [d][n] bf16
__device__ __nv_bfloat16 g_E[(size_t)NX * NN];          // 128 MB masked exp'd scores
__device__ float g_rowsum4[NSPLIT * NX];                // per-column-split partials

// ---------------- portable helpers ----------------
__device__ __forceinline__ uint32_t smem_u32(const void* p) {
    uint32_t a;
    asm("{ .reg .u64 t; cvta.to.shared.u64 t, %1; cvt.u32.u64 %0, t; }" : "=r"(a) : "l"(p));
    return a;
}
#define CP16(dst, src) \
    asm volatile("cp.async.cg.shared.global [%0], [%1], 16;" :: "r"(dst), "l"(src))
#define CP_COMMIT() asm volatile("cp.async.commit_group;" ::: "memory")
#define CP_WAIT1()  asm volatile("cp.async.wait_group 1;" ::: "memory")
#define CP_WAIT2()  asm volatile("cp.async.wait_group 2;" ::: "memory")

#define SW128(off) ((off) ^ (((off) >> 3) & 0x70))

#define LDMX4(r0, r1, r2, r3, addr) \
    asm volatile("ldmatrix.sync.aligned.m8n8.x4.shared.b16 {%0,%1,%2,%3}, [%4];" \
                 : "=r"(r0), "=r"(r1), "=r"(r2), "=r"(r3) : "r"(addr))

#define MMA16816(c, a, b) \
    asm volatile("mma.sync.aligned.m16n8k16.row.col.f32.bf16.bf16.f32 " \
                 "{%0,%1,%2,%3}, {%4,%5,%6,%7}, {%8,%9}, {%0,%1,%2,%3};" \
                 : "+f"((c)[0]), "+f"((c)[1]), "+f"((c)[2]), "+f"((c)[3]) \
                 : "r"((a)[0]), "r"((a)[1]), "r"((a)[2]), "r"((a)[3]), \
                   "r"((b)[0]), "r"((b)[1]))

__device__ __forceinline__ uint32_t bf2_hi(float a, float b) {
    __nv_bfloat162 p = __floats2bfloat162_rn(a, b);
    return reinterpret_cast<uint32_t&>(p);
}
__device__ __forceinline__ void split2(float a, float b, uint32_t &hi, uint32_t &lo) {
    __nv_bfloat16 ah = __float2bfloat16_rn(a);
    __nv_bfloat16 bh = __float2bfloat16_rn(b);
    __nv_bfloat162 h; h.x = ah; h.y = bh;
    __nv_bfloat162 l = __floats2bfloat162_rn(a - __bfloat162float(ah),
                                             b - __bfloat162float(bh));
    hi = reinterpret_cast<uint32_t&>(h);
    lo = reinterpret_cast<uint32_t&>(l);
}

// Fast exp on the FMA/ALU pipes (no MUFU). rel err ~2e-6 on |w| <~ 20.
__device__ __forceinline__ float fast_exp(float w) {
    const float L2E = 1.4426950408889634f;
    float t  = fmaf(w, L2E, 12582912.0f);
    int   n  = __float_as_int(t) - 0x4B400000;
    float nf = t - 12582912.0f;
    float f  = fmaf(w, L2E, -nf);
    float p  = fmaf(f, 0.0013333558f, 0.0096181291f);
    p = fmaf(f, p, 0.0555041087f);
    p = fmaf(f, p, 0.2402265069f);
    p = fmaf(f, p, 0.6931471806f);
    p = fmaf(f, p, 1.0f);
    return __int_as_float(__float_as_int(p) + (n << 23));
}

// =====================================================================
// K1: fused MLP (R10 128-row version): att = tanh(A@W1+b1)@W2+b2 -> bf16
// =====================================================================
__global__ __launch_bounds__(256)
void k_mlp(const float* __restrict__ A0, const float* __restrict__ W10,
           const float* __restrict__ b10, const float* __restrict__ W20,
           const float* __restrict__ b20, __nv_bfloat16* __restrict__ att0,
           const float* __restrict__ A1, const float* __restrict__ W11,
           const float* __restrict__ b11, const float* __restrict__ W21,
           const float* __restrict__ b21, __nv_bfloat16* __restrict__ att1) {
    __shared__ float As[32][132];
    __shared__ float Ws[32][32];
    __shared__ float W2s[32][33];
    __shared__ float Hs[128][36];
    const int tid  = threadIdx.x;
    const int which = (int)(blockIdx.x >> 6);
    const int row0 = (int)(blockIdx.x & 63) * 128;
    const float* A  = which ? A1  : A0;
    const float* W1 = which ? W11 : W10;
    const float* b1 = which ? b11 : b10;
    const float* W2 = which ? W21 : W20;
    const float* b2 = which ? b21 : b20;
    __nv_bfloat16* att = which ? att1 : att0;

    const int ty = tid / 8, tx = tid % 8;
    float acc[4][4] = {};

    #pragma unroll
    for (int p = 0; p < 4; p++) {
        int i = p * 256 + tid;
        W2s[i >> 5][i & 31] = W2[i];
    }

    for (int k0 = 0; k0 < DIN; k0 += 32) {
        #pragma unroll
        for (int p = 0; p < 4; p++) {
            int r  = p * 32 + tid / 8;
            int kq = (tid % 8) * 4;
            float4 v = *(const float4*)&A[(size_t)(row0 + r) * DIN + k0 + kq];
            As[kq + 0][r] = v.x; As[kq + 1][r] = v.y;
            As[kq + 2][r] = v.z; As[kq + 3][r] = v.w;
        }
        {
            int k = tid / 8, c4 = (tid % 8) * 4;
            *(float4*)&Ws[k][c4] = *(const float4*)&W1[(size_t)(k0 + k) * DH + c4];
        }
        __syncthreads();
        #pragma unroll
        for (int k = 0; k < 32; k++) {
            float4 a = *(const float4*)&As[k][ty * 4];
            float4 w = *(const float4*)&Ws[k][tx * 4];
            float av[4] = {a.x, a.y, a.z, a.w};
            float wv[4] = {w.x, w.y, w.z, w.w};
            #pragma unroll
            for (int r = 0; r < 4; r++)
                #pragma unroll
                for (int c = 0; c < 4; c++)
                    acc[r][c] += av[r] * wv[c];
        }
        __syncthreads();
    }
    #pragma unroll
    for (int r = 0; r < 4; r++)
        #pragma unroll
        for (int c = 0; c < 4; c++)
            Hs[ty * 4 + r][tx * 4 + c] = tanhf(acc[r][c] + b1[tx * 4 + c]);
    __syncthreads();

    {
        const int row = tid >> 1;
        const int cb  = (tid & 1) * 16;
        float s[16];
        #pragma unroll
        for (int j = 0; j < 16; j++) s[j] = b2[cb + j];
        #pragma unroll
        for (int k = 0; k < 32; k++) {
            float hv = Hs[row][k];
            #pragma unroll
            for (int j = 0; j < 16; j++) s[j] += hv * W2s[k][cb + j];
        }
        uint32_t ob[8];
        #pragma unroll
        for (int j2 = 0; j2 < 8; j2++) ob[j2] = bf2_hi(s[2 * j2], s[2 * j2 + 1]);
        uint4 u0 = {ob[0], ob[1], ob[2], ob[3]};
        uint4 u1 = {ob[4], ob[5], ob[6], ob[7]};
        *(uint4*)&att[(size_t)(row0 + row) * DH + cb]     = u0;
        *(uint4*)&att[(size_t)(row0 + row) * DH + cb + 8] = u1;
    }
}

// =====================================================================
// K2a: fc_x via split-bf16 HMMA (3-term: xh*wh + xh*wl + xl*wh).
// =====================================================================
#define FC_REG   10240
#define FC_STAGE (4 * FC_REG)
#define FC_SMEM  (2 * FC_STAGE)

__device__ __forceinline__ void fcx_ldg(const float* __restrict__ X,
                                        const float* __restrict__ W,
                                        int row0, int d0, int kc, int tid,
                                        float xv[8], float wv[8]) {
    const int r = tid >> 2, seg = tid & 3;
    const float* xs = &X[(size_t)(row0 + r) * DIN + kc * 32 + seg * 8];
    *(float4*)&xv[0] = *(const float4*)&xs[0];
    *(float4*)&xv[4] = *(const float4*)&xs[4];
    const int wd = tid & 127, wk = (tid >> 7) * 8;
    #pragma unroll
    for (int j = 0; j < 8; j++)
        wv[j] = W[(size_t)(kc * 32 + wk + j) * DOUT + d0 + wd];
}
__device__ __forceinline__ void fcx_sts(char* base, int tid,
                                        const float xv[8], const float wv[8]) {
    char* sAh = base;
    char* sAl = base + FC_REG;
    char* sBh = base + 2 * FC_REG;
    char* sBl = base + 3 * FC_REG;
    const int r = tid >> 2, seg = tid & 3;
    uint32_t h[4], lo[4];
    #pragma unroll
    for (int j = 0; j < 4; j++) split2(xv[2 * j], xv[2 * j + 1], h[j], lo[j]);
    *(uint4*)&sAh[r * 80 + seg * 16] = make_uint4(h[0], h[1], h[2], h[3]);
    *(uint4*)&sAl[r * 80 + seg * 16] = make_uint4(lo[0], lo[1], lo[2], lo[3]);
    const int wd = tid & 127, wk = (tid >> 7) * 8;
    #pragma unroll
    for (int j = 0; j < 4; j++) split2(wv[2 * j], wv[2 * j + 1], h[j], lo[j]);
    *(uint4*)&sBh[wd * 80 + wk * 2] = make_uint4(h[0], h[1], h[2], h[3]);
    *(uint4*)&sBl[wd * 80 + wk * 2] = make_uint4(lo[0], lo[1], lo[2], lo[3]);
}

__global__ __launch_bounds__(512)
void k_fcx_mma(const float* __restrict__ X, const float* __restrict__ W,
               const float* __restrict__ bias, float* __restrict__ outp) {
    extern __shared__ __align__(16) char fcsm[];
    const int tid = threadIdx.x, wid = tid >> 5, l = tid & 31;
    const int row0 = (int)(blockIdx.x >> 1) * 128;
    const int d0   = (int)(blockIdx.x & 1) * 128;
    const int wm = (wid >> 2) * 32, wn = (wid & 3) * 32;

    float acc[2][4][4];
    #pragma unroll
    for (int t = 0; t < 2; t++)
        #pragma unroll
        for (int u = 0; u < 4; u++)
            #pragma unroll
            for (int c = 0; c < 4; c++) acc[t][u][c] = 0.f;

    float xv[8], wv[8];
    fcx_ldg(X, W, row0, d0, 0, tid, xv, wv);
    fcx_sts(fcsm, tid, xv, wv);
    fcx_ldg(X, W, row0, d0, 1, tid, xv, wv);

    const int lm16 = l & 15, lhi = (l >> 4) * 16;
    const int bn = (l & 7) + ((l >> 4) << 3), bk16 = ((l >> 3) & 1) * 16;

    for (int i = 0; i < 16; i++) {
        __syncthreads();
        if (i + 1 < 16) fcx_sts(fcsm + ((i + 1) & 1) * FC_STAGE, tid, xv, wv);
        if (i + 2 < 16) fcx_ldg(X, W, row0, d0, i + 2, tid, xv, wv);
        __syncthreads();

        char* base = fcsm + (i & 1) * FC_STAGE;
        const uint32_t Ah = smem_u32(base);
        const uint32_t Al = Ah + FC_REG;
        const uint32_t Bh = Ah + 2 * FC_REG;
        const uint32_t Bl = Ah + 3 * FC_REG;
        #pragma unroll
        for (int kk = 0; kk < 2; kk++) {
            uint32_t ah[2][4], al[2][4];
            #pragma unroll
            for (int t = 0; t < 2; t++) {
                uint32_t off = (uint32_t)((wm + t * 16 + lm16) * 80 + kk * 32 + lhi);
                LDMX4(ah[t][0], ah[t][1], ah[t][2], ah[t][3], Ah + off);
                LDMX4(al[t][0], al[t][1], al[t][2], al[t][3], Al + off);
            }
            #pragma unroll
            for (int u2 = 0; u2 < 2; u2++) {
                uint32_t off = (uint32_t)((wn + u2 * 16 + bn) * 80 + kk * 32 + bk16);
                uint32_t h0, h1, h2, h3, l0, l1, l2, l3;
                LDMX4(h0, h1, h2, h3, Bh + off);
                LDMX4(l0, l1, l2, l3, Bl + off);
                uint32_t bh0[2] = {h0, h1}, bh1[2] = {h2, h3};
                uint32_t bl0[2] = {l0, l1}, bl1[2] = {l2, l3};
                #pragma unroll
                for (int t = 0; t < 2; t++) {
                    MMA16816(acc[t][2 * u2],     ah[t], bh0);
                    MMA16816(acc[t][2 * u2],     ah[t], bl0);
                    MMA16816(acc[t][2 * u2],     al[t], bh0);
                    MMA16816(acc[t][2 * u2 + 1], ah[t], bh1);
                    MMA16816(acc[t][2 * u2 + 1], ah[t], bl1);
                    MMA16816(acc[t][2 * u2 + 1], al[t], bh1);
                }
            }
        }
    }

    #pragma unroll
    for (int t = 0; t < 2; t++) {
        int ra = row0 + wm + t * 16 + (l >> 2);
        int rb = ra + 8;
        #pragma unroll
        for (int u = 0; u < 4; u++) {
            int col = d0 + wn + u * 8 + (l & 3) * 2;
            float b0v = bias[col], b1v = bias[col + 1];
            float2 v0 = {acc[t][u][0] + b0v, acc[t][u][1] + b1v};
            float2 v1 = {acc[t][u][2] + b0v, acc[t][u][3] + b1v};
            *(float2*)&outp[(size_t)ra * (2 * DOUT) + col] = v0;
            *(float2*)&outp[(size_t)rb * (2 * DOUT) + col] = v1;
        }
    }
}

// =====================================================================
// K2b: value GEMM on HMMA, transposed output into g_valueT[d][n] bf16.
// =====================================================================
__device__ __forceinline__ void gemm_ldg(const float* __restrict__ X,
                                         const float* __restrict__ W,
                                         int row0, int d0, int kc, int tid,
                                         float4 xv[4], float wv[16]) {
    #pragma unroll
    for (int p = 0; p < 4; p++)
        xv[p] = *(const float4*)&X[(size_t)(row0 + p * 32 + (tid >> 3)) * DIN
                                   + kc * 32 + (tid & 7) * 4];
    const int wd = tid & 127, wkh = tid >> 7;
    #pragma unroll
    for (int k2 = 0; k2 < 16; k2++)
        wv[k2] = W[(size_t)(kc * 32 + wkh * 16 + k2) * DOUT + d0 + wd];
}
__device__ __forceinline__ void gemm_sts(char* sA, char* sB, int tid,
                                         const float4 xv[4], const float wv[16]) {
    #pragma unroll
    for (int p = 0; p < 4; p++) {
        uint2 u;
        u.x = bf2_hi(xv[p].x, xv[p].y);
        u.y = bf2_hi(xv[p].z, xv[p].w);
        *(uint2*)&sA[(p * 32 + (tid >> 3)) * 80 + (tid & 7) * 8] = u;
    }
    const int wd = tid & 127, wkh = tid >> 7;
    #pragma unroll
    for (int j = 0; j < 8; j++)
        *(uint32_t*)&sB[wd * 80 + wkh * 32 + j * 4] = bf2_hi(wv[2 * j], wv[2 * j + 1]);
}

__global__ __launch_bounds__(256)
void k_value_mma(const float* __restrict__ X, const float* __restrict__ W,
                 const float* __restrict__ bias) {
    __shared__ __align__(16) char sA[2][128 * 80];
    __shared__ __align__(16) char sB[2][128 * 80];
    const int tid = threadIdx.x, wid = tid >> 5, l = tid & 31;
    const int row0 = (int)(blockIdx.x >> 1) * 128;
    const int d0   = (int)(blockIdx.x & 1) * 128;
    const int wm = (wid >> 1) * 32, wn = (wid & 1) * 64;

    float acc[2][8][4];
    #pragma unroll
    for (int t = 0; t < 2; t++)
        #pragma unroll
        for (int u = 0; u < 8; u++)
            #pragma unroll
            for (int c = 0; c < 4; c++) acc[t][u][c] = 0.f;

    float4 xv[4]; float wv[16];
    gemm_ldg(X, W, row0, d0, 0, tid, xv, wv);
    gemm_sts(sA[0], sB[0], tid, xv, wv);
    gemm_ldg(X, W, row0, d0, 1, tid, xv, wv);

    const int lm16 = l & 15, lhi = (l >> 4) * 16;
    const int bn = (l & 7) + ((l >> 4) << 3), bk16 = ((l >> 3) & 1) * 16;

    for (int i = 0; i < 16; i++) {
        __syncthreads();
        if (i + 1 < 16) gemm_sts(sA[(i + 1) & 1], sB[(i + 1) & 1], tid, xv, wv);
        if (i + 2 < 16) gemm_ldg(X, W, row0, d0, i + 2, tid, xv, wv);

        const int b = i & 1;
        const uint32_t Ab = smem_u32(sB[b]);   // transposed: A = W tile
        const uint32_t Bb = smem_u32(sA[b]);
        #pragma unroll
        for (int kk = 0; kk < 2; kk++) {
            uint32_t a[2][4];
            #pragma unroll
            for (int t = 0; t < 2; t++) {
                uint32_t off = (uint32_t)((wm + t * 16 + lm16) * 80 + kk * 32 + lhi);
                LDMX4(a[t][0], a[t][1], a[t][2], a[t][3], Ab + off);
            }
            #pragma unroll
            for (int u2 = 0; u2 < 4; u2++) {
                uint32_t off = (uint32_t)((wn + u2 * 16 + bn) * 80 + kk * 32 + bk16);
                uint32_t r0_, r1_, r2_, r3_;
                LDMX4(r0_, r1_, r2_, r3_, Bb + off);
                uint32_t b0[2] = {r0_, r1_}, b1[2] = {r2_, r3_};
                #pragma unroll
                for (int t = 0; t < 2; t++) {
                    MMA16816(acc[t][2 * u2],     a[t], b0);
                    MMA16816(acc[t][2 * u2 + 1], a[t], b1);
                }
            }
        }
    }

    #pragma unroll
    for (int t = 0; t < 2; t++) {
        int dr = d0 + wm + t * 16 + (l >> 2);
        float bA = bias[dr], bB = bias[dr + 8];
        #pragma unroll
        for (int u = 0; u < 8; u++) {
            int nc = row0 + wn + u * 8 + (l & 3) * 2;
            uint32_t pA = bf2_hi(acc[t][u][0] + bA, acc[t][u][1] + bA);
            uint32_t pB = bf2_hi(acc[t][u][2] + bB, acc[t][u][3] + bB);
            *(uint32_t*)&g_valueT[(size_t)dr * NN + nc]       = pA;
            *(uint32_t*)&g_valueT[(size_t)(dr + 8) * NN + nc] = pB;
        }
    }
}

// =====================================================================
// K3: HMMA score kernel (R10 config): column-split x4; E staged through
// XOR-swizzled SMEM then coalesced STG.128; 4 CTAs/SM.
// =====================================================================
__device__ __forceinline__ void score_loadn(uint32_t nbase, int tid, int c, int buf) {
    #pragma unroll
    for (int q = 0; q < 2; q++) {
        int u  = tid * 2 + q;
        int rr = u >> 2, seg = u & 3;
        uint32_t dst = nbase + (uint32_t)buf * 10240u + (uint32_t)(rr * 80 + seg * 16);
        const char* src = (const char*)g_nattb + ((size_t)c * 128 + rr) * 64 + seg * 16;
        CP16(dst, src);
    }
}

__global__ __launch_bounds__(256, 4)
void k_score_mma(const int* __restrict__ adj) {
    __shared__ __align__(16) char sN[3 * 128 * 80];
    __shared__ __align__(16) uint32_t sEw[2][2048];
    __shared__ float s_rsum[4][32];
    const int tid = threadIdx.x, wid = tid >> 5, l = tid & 31;
    const int row0 = (int)(blockIdx.x >> 2) * 32;
    const int sp   = (int)(blockIdx.x & 3);
    const int c0   = sp * 16;
    const int wm = (wid >> 2) * 16;
    const int h  = wid & 3;
    const int wn = h * 32;
    const uint32_t nb = smem_u32(sN);

    uint32_t a[2][4];
    {
        const int r  = row0 + wm + (l >> 2);
        const int kq = (l & 3) * 2;
        const uint32_t* X = (const uint32_t*)g_xattb;
        #pragma unroll
        for (int kk = 0; kk < 2; kk++) {
            a[kk][0] = X[(size_t)r * 16       + (kk * 16 + kq) / 2];
            a[kk][1] = X[(size_t)(r + 8) * 16 + (kk * 16 + kq) / 2];
            a[kk][2] = X[(size_t)r * 16       + (kk * 16 + kq + 8) / 2];
            a[kk][3] = X[(size_t)(r + 8) * 16 + (kk * 16 + kq + 8) / 2];
        }
    }

    float rs0 = 0.f, rs1 = 0.f;
    const int bn = (l & 7) + ((l >> 4) << 3), bk16 = ((l >> 3) & 1) * 16;
    const int r0g = row0 + wm + (l >> 2);
    const int rlo = wm + (l >> 2);
    const int swz = ((l >> 2) & 7) << 2;

    score_loadn(nb, tid, c0 + 0, 0); CP_COMMIT();
    score_loadn(nb, tid, c0 + 1, 1); CP_COMMIT();

    for (int i = 0; i < 16; i++) {
        CP_WAIT1();
        __syncthreads();
        if (i + 2 < 16) score_loadn(nb, tid, c0 + i + 2, (i + 2) % 3);
        CP_COMMIT();

        int2 adv[4][2];
        #pragma unroll
        for (int u = 0; u < 4; u++) {
            int cb = (c0 + i) * 128 + wn + u * 8 + (l & 3) * 2;
            adv[u][0] = *(const int2*)&adj[(size_t)r0g * NN + cb];
            adv[u][1] = *(const int2*)&adj[(size_t)(r0g + 8) * NN + cb];
        }

        float acc[4][4];
        #pragma unroll
        for (int u = 0; u < 4; u++)
            #pragma unroll
            for (int c = 0; c < 4; c++) acc[u][c] = 0.f;

        const uint32_t buf = nb + (uint32_t)(i % 3) * 10240u;
        #pragma unroll
        for (int kk = 0; kk < 2; kk++) {
            #pragma unroll
            for (int u2 = 0; u2 < 2; u2++) {
                uint32_t off = (uint32_t)((wn + u2 * 16 + bn) * 80 + kk * 32 + bk16);
                uint32_t r0_, r1_, r2_, r3_;
                LDMX4(r0_, r1_, r2_, r3_, buf + off);
                uint32_t b0[2] = {r0_, r1_}, b1[2] = {r2_, r3_};
                MMA16816(acc[2 * u2],     a[kk], b0);
                MMA16816(acc[2 * u2 + 1], a[kk], b1);
            }
        }

        #pragma unroll
        for (int u = 0; u < 4; u++) {
            const int colw = (wn >> 1) + u * 4 + (l & 3);
            {
                float s0 = acc[u][0], s1 = acc[u][1];
                float w0 = s0 > 0.f ? s0 : 0.01f * s0;
                float w1 = s1 > 0.f ? s1 : 0.01f * s1;
                float e0 = adv[u][0].x > 0 ? fast_exp(w0) : 0.f;
                float e1 = adv[u][0].y > 0 ? fast_exp(w1) : 0.f;
                rs0 += e0 + e1;
                sEw[i & 1][rlo * 64 + (colw ^ swz)] = bf2_hi(e0, e1);
            }
            {
                float s0 = acc[u][2], s1 = acc[u][3];
                float w0 = s0 > 0.f ? s0 : 0.01f * s0;
                float w1 = s1 > 0.f ? s1 : 0.01f * s1;
                float e0 = adv[u][1].x > 0 ? fast_exp(w0) : 0.f;
                float e1 = adv[u][1].y > 0 ? fast_exp(w1) : 0.f;
                rs1 += e0 + e1;
                sEw[i & 1][(rlo + 8) * 64 + (colw ^ swz)] = bf2_hi(e0, e1);
            }
        }
        __syncthreads();

        {
            const int row = tid >> 3;
            const int jb  = tid & 7;
            const int rsw = (row & 7) << 2;
            size_t gbase = (size_t)(row0 + row) * NN + (size_t)(c0 + i) * 128;
            #pragma unroll
            for (int hh = 0; hh < 2; hh++) {
                int blk = jb + hh * 8;
                int pos = (blk * 4) ^ rsw;
                uint4 v = *(uint4*)&sEw[i & 1][row * 64 + pos];
                *(uint4*)&g_E[gbase + blk * 8] = v;
            }
        }
    }

    rs0 += __shfl_xor_sync(0xffffffff, rs0, 1);
    rs0 += __shfl_xor_sync(0xffffffff, rs0, 2);
    rs1 += __shfl_xor_sync(0xffffffff, rs1, 1);
    rs1 += __shfl_xor_sync(0xffffffff, rs1, 2);
    if ((l & 3) == 0) {
        s_rsum[h][wm + (l >> 2)]     = rs0;
        s_rsum[h][wm + (l >> 2) + 8] = rs1;
    }
    __syncthreads();
    if (tid < 32)
        g_rowsum4[sp * NX + row0 + tid] =
            (s_rsum[0][tid] + s_rsum[1][tid]) + (s_rsum[2][tid] + s_rsum[3][tid]);
}

// =====================================================================
// K4: HMMA PV GEMM — ROW-split: 128 CTAs x 64 rows x 256 dout x full K.
// Normalized output written directly (no partials, no combine kernel).
// 512 threads, warps 4m(16 rows) x 4n(64 dout).
// =====================================================================
#define PV_BK     64
#define PV_NCH    (NN / PV_BK)       // 128
#define PV_STAGEB 40960              // 8KB E (64 rows) + 32KB V
#define PV_SMEM   (4 * PV_STAGEB + 1024)

__device__ __forceinline__ void pv_load(uint32_t tile, int tid, int row0, int c) {
    const size_t kb = (size_t)c * (PV_BK * 2);
    const uint32_t eb = tile + (uint32_t)(c & 3) * PV_STAGEB;
    const uint32_t vb = eb + 8192u;
    {   // E: 64 rows x 8 segs = 512 = 1 per thread
        int row = tid >> 3, j = tid & 7;
        CP16(eb + SW128((uint32_t)(row * 128 + j * 16)),
             (const char*)g_E + ((size_t)(row0 + row) * NN) * 2 + kb + (size_t)(j * 16));
    }
    #pragma unroll
    for (int p = 0; p < 4; p++) {    // V: 256 d-rows x 8 segs = 2048
        int u = p * 512 + tid;
        int row = u >> 3, j = u & 7;
        CP16(vb + SW128((uint32_t)(row * 128 + j * 16)),
             (const char*)g_valueT + ((size_t)row * NN) * 2 + kb + (size_t)(j * 16));
    }
}

__global__ __launch_bounds__(512, 1)
void k_pv_mma(float* __restrict__ out) {
    extern __shared__ __align__(16) char dynsmem[];
    const int tid = threadIdx.x;
    const int wid = tid >> 5;
    const int l   = tid & 31;
    const int row0 = (int)blockIdx.x * 64;
    const int wm0  = (wid >> 2) * 16;    // 4 m-groups x 16 rows
    const int wn0  = (wid & 3) * 64;     // 4 n-groups x 64 dout

    const uint32_t dynb = smem_u32(dynsmem);
    const uint32_t tile = (dynb + 1023u) & ~1023u;

    float acc[8][4];
    #pragma unroll
    for (int u = 0; u < 8; u++)
        #pragma unroll
        for (int c = 0; c < 4; c++) acc[u][c] = 0.f;

    pv_load(tile, tid, row0, 0); CP_COMMIT();
    pv_load(tile, tid, row0, 1); CP_COMMIT();
    pv_load(tile, tid, row0, 2); CP_COMMIT();

    const int lm16 = l & 15;
    const int lhi  = (l >> 4) * 16;
    const int bn   = (l & 7) + ((l >> 4) << 3);
    const int bk16 = ((l >> 3) & 1) * 16;

    for (int i = 0; i < PV_NCH; i++) {
        CP_WAIT2();
        __syncthreads();
        const uint32_t eb = tile + (uint32_t)(i & 3) * PV_STAGEB;
        const uint32_t vb = eb + 8192u;
        #pragma unroll
        for (int kk = 0; kk < 4; kk++) {
            uint32_t a[4];
            LDMX4(a[0], a[1], a[2], a[3],
                  eb + SW128((uint32_t)((wm0 + lm16) * 128 + kk * 32 + lhi)));
            #pragma unroll
            for (int u2 = 0; u2 < 4; u2++) {
                uint32_t off = (uint32_t)((wn0 + u2 * 16 + bn) * 128 + kk * 32 + bk16);
                uint32_t r0, r1, r2, r3;
                LDMX4(r0, r1, r2, r3, vb + SW128(off));
                uint32_t b0[2] = {r0, r1}, b1[2] = {r2, r3};
                MMA16816(acc[2 * u2],     a, b0);
                MMA16816(acc[2 * u2 + 1], a, b1);
            }
        }
        const int j = i + 3;
        if (j < PV_NCH) pv_load(tile, tid, row0, j);
        CP_COMMIT();
    }

    // epilogue: sum rowsum partials, normalize, direct store
    {
        int ra = row0 + wm0 + (l >> 2);
        int rb = ra + 8;
        float sa = (g_rowsum4[ra] + g_rowsum4[NX + ra]) +
                   (g_rowsum4[2 * NX + ra] + g_rowsum4[3 * NX + ra]);
        float sb = (g_rowsum4[rb] + g_rowsum4[NX + rb]) +
                   (g_rowsum4[2 * NX + rb] + g_rowsum4[3 * NX + rb]);
        float inva = 1.0f / sa;
        float invb = 1.0f / sb;
        #pragma unroll
        for (int u = 0; u < 8; u++) {
            int col = DOUT + wn0 + u * 8 + (l & 3) * 2;
            float2 v0 = {acc[u][0] * inva, acc[u][1] * inva};
            float2 v1 = {acc[u][2] * invb, acc[u][3] * invb};
            *(float2*)&out[(size_t)ra * (2 * DOUT) + col] = v0;
            *(float2*)&out[(size_t)rb * (2 * DOUT) + col] = v1;
        }
    }
}

// =====================================================================
// launch (single stream)
// =====================================================================
extern "C" void kernel_launch(void* const* d_in, const int* in_sizes, int n_in,
                              void* d_out, int out_size) {
    const float* x    = (const float*)d_in[0];
    const float* neigh= (const float*)d_in[1];
    const int*   adj  = (const int*)  d_in[2];
    const float* Wx1  = (const float*)d_in[3];
    const float* bx1  = (const float*)d_in[4];
    const float* Wx2  = (const float*)d_in[5];
    const float* bx2  = (const float*)d_in[6];
    const float* Wn1  = (const float*)d_in[7];
    const float* bn1  = (const float*)d_in[8];
    const float* Wn2  = (const float*)d_in[9];
    const float* bn2  = (const float*)d_in[10];
    const float* Wv   = (const float*)d_in[11];
    const float* bv   = (const float*)d_in[12];
    const float* Wfx  = (const float*)d_in[13];
    const float* bfx  = (const float*)d_in[14];
    float* out = (float*)d_out;

    __nv_bfloat16* xattb;
    __nv_bfloat16* nattb;
    cudaGetSymbolAddress((void**)&xattb, g_xattb);
    cudaGetSymbolAddress((void**)&nattb, g_nattb);

    cudaFuncSetAttribute(k_pv_mma, cudaFuncAttributeMaxDynamicSharedMemorySize, PV_SMEM);
    cudaFuncSetAttribute(k_fcx_mma, cudaFuncAttributeMaxDynamicSharedMemorySize, FC_SMEM);

    // fused attention MLPs (both branches in one grid) -> bf16 att
    k_mlp<<<2 * (NX / 128), 256>>>(neigh, Wn1, bn1, Wn2, bn2, nattb,
                                   x, Wx1, bx1, Wx2, bx2, xattb);
    // value (HMMA, transposed -> g_valueT); fc_x split-bf16 HMMA
    k_value_mma<<<128, 256>>>(neigh, Wv, bv);
    k_fcx_mma<<<128, 512, FC_SMEM>>>(x, Wfx, bfx, out);
    // HMMA scores + masked fast_exp + partial rowsums (column-split x4)
    k_score_mma<<<(NX / 32) * NSPLIT, 256>>>(adj);
    // HMMA PV (row-split, full K) -> normalized output directly
    k_pv_mma<<<NX / 64, 512, PV_SMEM>>>(out);
}

// round 17
// speedup vs baseline: 1.1169x; 1.1169x over previous
#include <cuda_runtime.h>
#include <cuda_bf16.h>
#include <cstdint>

#define NX   8192
#define NN   8192
#define DIN  512
#define DH   32
#define DOUT 256
#define NSPLIT 8
#define SCH    (64 / NSPLIT)     // chunks of 128 cols per score CTA = 8

// ---------------- scratch (static __device__: allocation-free) ----------------
__device__ __nv_bfloat16 g_xattb[NX * DH];              // bf16 att (x)
__device__ __nv_bfloat16 g_nattb[NN * DH];              // bf16 att (neigh)
__device__ __nv_bfloat16 g_valueT[(size_t)DOUT * NN];   // 4 MB, [d][n] bf16
__device__ __nv_bfloat16 g_E[(size_t)NX * NN];          // 128 MB masked exp'd scores
__device__ float g_rowsum4[NSPLIT * NX];                // per-column-split partials
__device__ float g_pvpart[2 * (size_t)NX * DOUT];       // 16 MB PV k-split partials

// ---------------- portable helpers ----------------
__device__ __forceinline__ uint32_t smem_u32(const void* p) {
    uint32_t a;
    asm("{ .reg .u64 t; cvta.to.shared.u64 t, %1; cvt.u32.u64 %0, t; }" : "=r"(a) : "l"(p));
    return a;
}
#define CP16(dst, src) \
    asm volatile("cp.async.cg.shared.global [%0], [%1], 16;" :: "r"(dst), "l"(src))
#define CP_COMMIT() asm volatile("cp.async.commit_group;" ::: "memory")
#define CP_WAIT1()  asm volatile("cp.async.wait_group 1;" ::: "memory")
#define CP_WAIT2()  asm volatile("cp.async.wait_group 2;" ::: "memory")

#define SW128(off) ((off) ^ (((off) >> 3) & 0x70))

#define LDMX4(r0, r1, r2, r3, addr) \
    asm volatile("ldmatrix.sync.aligned.m8n8.x4.shared.b16 {%0,%1,%2,%3}, [%4];" \
                 : "=r"(r0), "=r"(r1), "=r"(r2), "=r"(r3) : "r"(addr))

#define MMA16816(c, a, b) \
    asm volatile("mma.sync.aligned.m16n8k16.row.col.f32.bf16.bf16.f32 " \
                 "{%0,%1,%2,%3}, {%4,%5,%6,%7}, {%8,%9}, {%0,%1,%2,%3};" \
                 : "+f"((c)[0]), "+f"((c)[1]), "+f"((c)[2]), "+f"((c)[3]) \
                 : "r"((a)[0]), "r"((a)[1]), "r"((a)[2]), "r"((a)[3]), \
                   "r"((b)[0]), "r"((b)[1]))

__device__ __forceinline__ uint32_t bf2_hi(float a, float b) {
    __nv_bfloat162 p = __floats2bfloat162_rn(a, b);
    return reinterpret_cast<uint32_t&>(p);
}
__device__ __forceinline__ void split2(float a, float b, uint32_t &hi, uint32_t &lo) {
    __nv_bfloat16 ah = __float2bfloat16_rn(a);
    __nv_bfloat16 bh = __float2bfloat16_rn(b);
    __nv_bfloat162 h; h.x = ah; h.y = bh;
    __nv_bfloat162 l = __floats2bfloat162_rn(a - __bfloat162float(ah),
                                             b - __bfloat162float(bh));
    hi = reinterpret_cast<uint32_t&>(h);
    lo = reinterpret_cast<uint32_t&>(l);
}

// Fast exp on the FMA/ALU pipes (no MUFU). rel err ~2e-6 on |w| <~ 20.
__device__ __forceinline__ float fast_exp(float w) {
    const float L2E = 1.4426950408889634f;
    float t  = fmaf(w, L2E, 12582912.0f);
    int   n  = __float_as_int(t) - 0x4B400000;
    float nf = t - 12582912.0f;
    float f  = fmaf(w, L2E, -nf);
    float p  = fmaf(f, 0.0013333558f, 0.0096181291f);
    p = fmaf(f, p, 0.0555041087f);
    p = fmaf(f, p, 0.2402265069f);
    p = fmaf(f, p, 0.6931471806f);
    p = fmaf(f, p, 1.0f);
    return __int_as_float(__float_as_int(p) + (n << 23));
}

// =====================================================================
// K1: fused MLP: att = tanh(A @ W1 + b1) @ W2 + b2 -> bf16
// =====================================================================
__global__ __launch_bounds__(256)
void k_mlp(const float* __restrict__ A0, const float* __restrict__ W10,
           const float* __restrict__ b10, const float* __restrict__ W20,
           const float* __restrict__ b20, __nv_bfloat16* __restrict__ att0,
           const float* __restrict__ A1, const float* __restrict__ W11,
           const float* __restrict__ b11, const float* __restrict__ W21,
           const float* __restrict__ b21, __nv_bfloat16* __restrict__ att1) {
    __shared__ float As[32][132];
    __shared__ float Ws[32][32];
    __shared__ float W2s[32][33];
    __shared__ float Hs[128][36];
    const int tid  = threadIdx.x;
    const int which = (int)(blockIdx.x >> 6);
    const int row0 = (int)(blockIdx.x & 63) * 128;
    const float* A  = which ? A1  : A0;
    const float* W1 = which ? W11 : W10;
    const float* b1 = which ? b11 : b10;
    const float* W2 = which ? W21 : W20;
    const float* b2 = which ? b21 : b20;
    __nv_bfloat16* att = which ? att1 : att0;

    const int ty = tid / 8, tx = tid % 8;
    float acc[4][4] = {};

    #pragma unroll
    for (int p = 0; p < 4; p++) {
        int i = p * 256 + tid;
        W2s[i >> 5][i & 31] = W2[i];
    }

    for (int k0 = 0; k0 < DIN; k0 += 32) {
        #pragma unroll
        for (int p = 0; p < 4; p++) {
            int r  = p * 32 + tid / 8;
            int kq = (tid % 8) * 4;
            float4 v = *(const float4*)&A[(size_t)(row0 + r) * DIN + k0 + kq];
            As[kq + 0][r] = v.x; As[kq + 1][r] = v.y;
            As[kq + 2][r] = v.z; As[kq + 3][r] = v.w;
        }
        {
            int k = tid / 8, c4 = (tid % 8) * 4;
            *(float4*)&Ws[k][c4] = *(const float4*)&W1[(size_t)(k0 + k) * DH + c4];
        }
        __syncthreads();
        #pragma unroll
        for (int k = 0; k < 32; k++) {
            float4 a = *(const float4*)&As[k][ty * 4];
            float4 w = *(const float4*)&Ws[k][tx * 4];
            float av[4] = {a.x, a.y, a.z, a.w};
            float wv[4] = {w.x, w.y, w.z, w.w};
            #pragma unroll
            for (int r = 0; r < 4; r++)
                #pragma unroll
                for (int c = 0; c < 4; c++)
                    acc[r][c] += av[r] * wv[c];
        }
        __syncthreads();
    }
    #pragma unroll
    for (int r = 0; r < 4; r++)
        #pragma unroll
        for (int c = 0; c < 4; c++)
            Hs[ty * 4 + r][tx * 4 + c] = tanhf(acc[r][c] + b1[tx * 4 + c]);
    __syncthreads();

    {
        const int row = tid >> 1;
        const int cb  = (tid & 1) * 16;
        float s[16];
        #pragma unroll
        for (int j = 0; j < 16; j++) s[j] = b2[cb + j];
        #pragma unroll
        for (int k = 0; k < 32; k++) {
            float hv = Hs[row][k];
            #pragma unroll
            for (int j = 0; j < 16; j++) s[j] += hv * W2s[k][cb + j];
        }
        uint32_t ob[8];
        #pragma unroll
        for (int j2 = 0; j2 < 8; j2++) ob[j2] = bf2_hi(s[2 * j2], s[2 * j2 + 1]);
        uint4 u0 = {ob[0], ob[1], ob[2], ob[3]};
        uint4 u1 = {ob[4], ob[5], ob[6], ob[7]};
        *(uint4*)&att[(size_t)(row0 + row) * DH + cb]     = u0;
        *(uint4*)&att[(size_t)(row0 + row) * DH + cb + 8] = u1;
    }
}

// =====================================================================
// K2a: fc_x via split-bf16 HMMA (3-term: xh*wh + xh*wl + xl*wh).
// =====================================================================
#define FC_REG   10240
#define FC_STAGE (4 * FC_REG)
#define FC_SMEM  (2 * FC_STAGE)

__device__ __forceinline__ void fcx_ldg(const float* __restrict__ X,
                                        const float* __restrict__ W,
                                        int row0, int d0, int kc, int tid,
                                        float xv[8], float wv[8]) {
    const int r = tid >> 2, seg = tid & 3;
    const float* xs = &X[(size_t)(row0 + r) * DIN + kc * 32 + seg * 8];
    *(float4*)&xv[0] = *(const float4*)&xs[0];
    *(float4*)&xv[4] = *(const float4*)&xs[4];
    const int wd = tid & 127, wk = (tid >> 7) * 8;
    #pragma unroll
    for (int j = 0; j < 8; j++)
        wv[j] = W[(size_t)(kc * 32 + wk + j) * DOUT + d0 + wd];
}
__device__ __forceinline__ void fcx_sts(char* base, int tid,
                                        const float xv[8], const float wv[8]) {
    char* sAh = base;
    char* sAl = base + FC_REG;
    char* sBh = base + 2 * FC_REG;
    char* sBl = base + 3 * FC_REG;
    const int r = tid >> 2, seg = tid & 3;
    uint32_t h[4], lo[4];
    #pragma unroll
    for (int j = 0; j < 4; j++) split2(xv[2 * j], xv[2 * j + 1], h[j], lo[j]);
    *(uint4*)&sAh[r * 80 + seg * 16] = make_uint4(h[0], h[1], h[2], h[3]);
    *(uint4*)&sAl[r * 80 + seg * 16] = make_uint4(lo[0], lo[1], lo[2], lo[3]);
    const int wd = tid & 127, wk = (tid >> 7) * 8;
    #pragma unroll
    for (int j = 0; j < 4; j++) split2(wv[2 * j], wv[2 * j + 1], h[j], lo[j]);
    *(uint4*)&sBh[wd * 80 + wk * 2] = make_uint4(h[0], h[1], h[2], h[3]);
    *(uint4*)&sBl[wd * 80 + wk * 2] = make_uint4(lo[0], lo[1], lo[2], lo[3]);
}

__global__ __launch_bounds__(512)
void k_fcx_mma(const float* __restrict__ X, const float* __restrict__ W,
               const float* __restrict__ bias, float* __restrict__ outp) {
    extern __shared__ __align__(16) char fcsm[];
    const int tid = threadIdx.x, wid = tid >> 5, l = tid & 31;
    const int row0 = (int)(blockIdx.x >> 1) * 128;
    const int d0   = (int)(blockIdx.x & 1) * 128;
    const int wm = (wid >> 2) * 32, wn = (wid & 3) * 32;

    float acc[2][4][4];
    #pragma unroll
    for (int t = 0; t < 2; t++)
        #pragma unroll
        for (int u = 0; u < 4; u++)
            #pragma unroll
            for (int c = 0; c < 4; c++) acc[t][u][c] = 0.f;

    float xv[8], wv[8];
    fcx_ldg(X, W, row0, d0, 0, tid, xv, wv);
    fcx_sts(fcsm, tid, xv, wv);
    fcx_ldg(X, W, row0, d0, 1, tid, xv, wv);

    const int lm16 = l & 15, lhi = (l >> 4) * 16;
    const int bn = (l & 7) + ((l >> 4) << 3), bk16 = ((l >> 3) & 1) * 16;

    for (int i = 0; i < 16; i++) {
        __syncthreads();
        if (i + 1 < 16) fcx_sts(fcsm + ((i + 1) & 1) * FC_STAGE, tid, xv, wv);
        if (i + 2 < 16) fcx_ldg(X, W, row0, d0, i + 2, tid, xv, wv);
        __syncthreads();

        char* base = fcsm + (i & 1) * FC_STAGE;
        const uint32_t Ah = smem_u32(base);
        const uint32_t Al = Ah + FC_REG;
        const uint32_t Bh = Ah + 2 * FC_REG;
        const uint32_t Bl = Ah + 3 * FC_REG;
        #pragma unroll
        for (int kk = 0; kk < 2; kk++) {
            uint32_t ah[2][4], al[2][4];
            #pragma unroll
            for (int t = 0; t < 2; t++) {
                uint32_t off = (uint32_t)((wm + t * 16 + lm16) * 80 + kk * 32 + lhi);
                LDMX4(ah[t][0], ah[t][1], ah[t][2], ah[t][3], Ah + off);
                LDMX4(al[t][0], al[t][1], al[t][2], al[t][3], Al + off);
            }
            #pragma unroll
            for (int u2 = 0; u2 < 2; u2++) {
                uint32_t off = (uint32_t)((wn + u2 * 16 + bn) * 80 + kk * 32 + bk16);
                uint32_t h0, h1, h2, h3, l0, l1, l2, l3;
                LDMX4(h0, h1, h2, h3, Bh + off);
                LDMX4(l0, l1, l2, l3, Bl + off);
                uint32_t bh0[2] = {h0, h1}, bh1[2] = {h2, h3};
                uint32_t bl0[2] = {l0, l1}, bl1[2] = {l2, l3};
                #pragma unroll
                for (int t = 0; t < 2; t++) {
                    MMA16816(acc[t][2 * u2],     ah[t], bh0);
                    MMA16816(acc[t][2 * u2],     ah[t], bl0);
                    MMA16816(acc[t][2 * u2],     al[t], bh0);
                    MMA16816(acc[t][2 * u2 + 1], ah[t], bh1);
                    MMA16816(acc[t][2 * u2 + 1], ah[t], bl1);
                    MMA16816(acc[t][2 * u2 + 1], al[t], bh1);
                }
            }
        }
    }

    #pragma unroll
    for (int t = 0; t < 2; t++) {
        int ra = row0 + wm + t * 16 + (l >> 2);
        int rb = ra + 8;
        #pragma unroll
        for (int u = 0; u < 4; u++) {
            int col = d0 + wn + u * 8 + (l & 3) * 2;
            float b0v = bias[col], b1v = bias[col + 1];
            float2 v0 = {acc[t][u][0] + b0v, acc[t][u][1] + b1v};
            float2 v1 = {acc[t][u][2] + b0v, acc[t][u][3] + b1v};
            *(float2*)&outp[(size_t)ra * (2 * DOUT) + col] = v0;
            *(float2*)&outp[(size_t)rb * (2 * DOUT) + col] = v1;
        }
    }
}

// =====================================================================
// K2b: value GEMM on HMMA, transposed output into g_valueT[d][n] bf16.
// =====================================================================
__device__ __forceinline__ void gemm_ldg(const float* __restrict__ X,
                                         const float* __restrict__ W,
                                         int row0, int d0, int kc, int tid,
                                         float4 xv[4], float wv[16]) {
    #pragma unroll
    for (int p = 0; p < 4; p++)
        xv[p] = *(const float4*)&X[(size_t)(row0 + p * 32 + (tid >> 3)) * DIN
                                   + kc * 32 + (tid & 7) * 4];
    const int wd = tid & 127, wkh = tid >> 7;
    #pragma unroll
    for (int k2 = 0; k2 < 16; k2++)
        wv[k2] = W[(size_t)(kc * 32 + wkh * 16 + k2) * DOUT + d0 + wd];
}
__device__ __forceinline__ void gemm_sts(char* sA, char* sB, int tid,
                                         const float4 xv[4], const float wv[16]) {
    #pragma unroll
    for (int p = 0; p < 4; p++) {
        uint2 u;
        u.x = bf2_hi(xv[p].x, xv[p].y);
        u.y = bf2_hi(xv[p].z, xv[p].w);
        *(uint2*)&sA[(p * 32 + (tid >> 3)) * 80 + (tid & 7) * 8] = u;
    }
    const int wd = tid & 127, wkh = tid >> 7;
    #pragma unroll
    for (int j = 0; j < 8; j++)
        *(uint32_t*)&sB[wd * 80 + wkh * 32 + j * 4] = bf2_hi(wv[2 * j], wv[2 * j + 1]);
}

__global__ __launch_bounds__(256)
void k_value_mma(const float* __restrict__ X, const float* __restrict__ W,
                 const float* __restrict__ bias) {
    __shared__ __align__(16) char sA[2][128 * 80];
    __shared__ __align__(16) char sB[2][128 * 80];
    const int tid = threadIdx.x, wid = tid >> 5, l = tid & 31;
    const int row0 = (int)(blockIdx.x >> 1) * 128;
    const int d0   = (int)(blockIdx.x & 1) * 128;
    const int wm = (wid >> 1) * 32, wn = (wid & 1) * 64;

    float acc[2][8][4];
    #pragma unroll
    for (int t = 0; t < 2; t++)
        #pragma unroll
        for (int u = 0; u < 8; u++)
            #pragma unroll
            for (int c = 0; c < 4; c++) acc[t][u][c] = 0.f;

    float4 xv[4]; float wv[16];
    gemm_ldg(X, W, row0, d0, 0, tid, xv, wv);
    gemm_sts(sA[0], sB[0], tid, xv, wv);
    gemm_ldg(X, W, row0, d0, 1, tid, xv, wv);

    const int lm16 = l & 15, lhi = (l >> 4) * 16;
    const int bn = (l & 7) + ((l >> 4) << 3), bk16 = ((l >> 3) & 1) * 16;

    for (int i = 0; i < 16; i++) {
        __syncthreads();
        if (i + 1 < 16) gemm_sts(sA[(i + 1) & 1], sB[(i + 1) & 1], tid, xv, wv);
        if (i + 2 < 16) gemm_ldg(X, W, row0, d0, i + 2, tid, xv, wv);

        const int b = i & 1;
        const uint32_t Ab = smem_u32(sB[b]);   // transposed: A = W tile
        const uint32_t Bb = smem_u32(sA[b]);
        #pragma unroll
        for (int kk = 0; kk < 2; kk++) {
            uint32_t a[2][4];
            #pragma unroll
            for (int t = 0; t < 2; t++) {
                uint32_t off = (uint32_t)((wm + t * 16 + lm16) * 80 + kk * 32 + lhi);
                LDMX4(a[t][0], a[t][1], a[t][2], a[t][3], Ab + off);
            }
            #pragma unroll
            for (int u2 = 0; u2 < 4; u2++) {
                uint32_t off = (uint32_t)((wn + u2 * 16 + bn) * 80 + kk * 32 + bk16);
                uint32_t r0_, r1_, r2_, r3_;
                LDMX4(r0_, r1_, r2_, r3_, Bb + off);
                uint32_t b0[2] = {r0_, r1_}, b1[2] = {r2_, r3_};
                #pragma unroll
                for (int t = 0; t < 2; t++) {
                    MMA16816(acc[t][2 * u2],     a[t], b0);
                    MMA16816(acc[t][2 * u2 + 1], a[t], b1);
                }
            }
        }
    }

    #pragma unroll
    for (int t = 0; t < 2; t++) {
        int dr = d0 + wm + t * 16 + (l >> 2);
        float bA = bias[dr], bB = bias[dr + 8];
        #pragma unroll
        for (int u = 0; u < 8; u++) {
            int nc = row0 + wn + u * 8 + (l & 3) * 2;
            uint32_t pA = bf2_hi(acc[t][u][0] + bA, acc[t][u][1] + bA);
            uint32_t pB = bf2_hi(acc[t][u][2] + bB, acc[t][u][3] + bB);
            *(uint32_t*)&g_valueT[(size_t)dr * NN + nc]       = pA;
            *(uint32_t*)&g_valueT[(size_t)(dr + 8) * NN + nc] = pB;
        }
    }
}

// =====================================================================
// K3: HMMA score kernel — column-split x8 (better wave quantization);
// E staged through XOR-swizzled SMEM then coalesced STG.128; 4 CTAs/SM.
// =====================================================================
__device__ __forceinline__ void score_loadn(uint32_t nbase, int tid, int c, int buf) {
    #pragma unroll
    for (int q = 0; q < 2; q++) {
        int u  = tid * 2 + q;
        int rr = u >> 2, seg = u & 3;
        uint32_t dst = nbase + (uint32_t)buf * 10240u + (uint32_t)(rr * 80 + seg * 16);
        const char* src = (const char*)g_nattb + ((size_t)c * 128 + rr) * 64 + seg * 16;
        CP16(dst, src);
    }
}

__global__ __launch_bounds__(256, 4)
void k_score_mma(const int* __restrict__ adj) {
    __shared__ __align__(16) char sN[3 * 128 * 80];
    __shared__ __align__(16) uint32_t sEw[2][2048];   // 2 x 32 rows x 64 words
    __shared__ float s_rsum[4][32];
    const int tid = threadIdx.x, wid = tid >> 5, l = tid & 31;
    const int row0 = (int)(blockIdx.x >> 3) * 32;
    const int sp   = (int)(blockIdx.x & 7);
    const int c0   = sp * SCH;
    const int wm = (wid >> 2) * 16;
    const int h  = wid & 3;
    const int wn = h * 32;
    const uint32_t nb = smem_u32(sN);

    uint32_t a[2][4];
    {
        const int r  = row0 + wm + (l >> 2);
        const int kq = (l & 3) * 2;
        const uint32_t* X = (const uint32_t*)g_xattb;
        #pragma unroll
        for (int kk = 0; kk < 2; kk++) {
            a[kk][0] = X[(size_t)r * 16       + (kk * 16 + kq) / 2];
            a[kk][1] = X[(size_t)(r + 8) * 16 + (kk * 16 + kq) / 2];
            a[kk][2] = X[(size_t)r * 16       + (kk * 16 + kq + 8) / 2];
            a[kk][3] = X[(size_t)(r + 8) * 16 + (kk * 16 + kq + 8) / 2];
        }
    }

    float rs0 = 0.f, rs1 = 0.f;
    const int bn = (l & 7) + ((l >> 4) << 3), bk16 = ((l >> 3) & 1) * 16;
    const int r0g = row0 + wm + (l >> 2);
    const int rlo = wm + (l >> 2);
    const int swz = ((l >> 2) & 7) << 2;

    score_loadn(nb, tid, c0 + 0, 0); CP_COMMIT();
    score_loadn(nb, tid, c0 + 1, 1); CP_COMMIT();

    for (int i = 0; i < SCH; i++) {
        CP_WAIT1();
        __syncthreads();                               // barrier A
        if (i + 2 < SCH) score_loadn(nb, tid, c0 + i + 2, (i + 2) % 3);
        CP_COMMIT();

        int2 adv[4][2];
        #pragma unroll
        for (int u = 0; u < 4; u++) {
            int cb = (c0 + i) * 128 + wn + u * 8 + (l & 3) * 2;
            adv[u][0] = *(const int2*)&adj[(size_t)r0g * NN + cb];
            adv[u][1] = *(const int2*)&adj[(size_t)(r0g + 8) * NN + cb];
        }

        float acc[4][4];
        #pragma unroll
        for (int u = 0; u < 4; u++)
            #pragma unroll
            for (int c = 0; c < 4; c++) acc[u][c] = 0.f;

        const uint32_t buf = nb + (uint32_t)(i % 3) * 10240u;
        #pragma unroll
        for (int kk = 0; kk < 2; kk++) {
            #pragma unroll
            for (int u2 = 0; u2 < 2; u2++) {
                uint32_t off = (uint32_t)((wn + u2 * 16 + bn) * 80 + kk * 32 + bk16);
                uint32_t r0_, r1_, r2_, r3_;
                LDMX4(r0_, r1_, r2_, r3_, buf + off);
                uint32_t b0[2] = {r0_, r1_}, b1[2] = {r2_, r3_};
                MMA16816(acc[2 * u2],     a[kk], b0);
                MMA16816(acc[2 * u2 + 1], a[kk], b1);
            }
        }

        #pragma unroll
        for (int u = 0; u < 4; u++) {
            const int colw = (wn >> 1) + u * 4 + (l & 3);
            {
                float s0 = acc[u][0], s1 = acc[u][1];
                float w0 = s0 > 0.f ? s0 : 0.01f * s0;
                float w1 = s1 > 0.f ? s1 : 0.01f * s1;
                float e0 = adv[u][0].x > 0 ? fast_exp(w0) : 0.f;
                float e1 = adv[u][0].y > 0 ? fast_exp(w1) : 0.f;
                rs0 += e0 + e1;
                sEw[i & 1][rlo * 64 + (colw ^ swz)] = bf2_hi(e0, e1);
            }
            {
                float s0 = acc[u][2], s1 = acc[u][3];
                float w0 = s0 > 0.f ? s0 : 0.01f * s0;
                float w1 = s1 > 0.f ? s1 : 0.01f * s1;
                float e0 = adv[u][1].x > 0 ? fast_exp(w0) : 0.f;
                float e1 = adv[u][1].y > 0 ? fast_exp(w1) : 0.f;
                rs1 += e0 + e1;
                sEw[i & 1][(rlo + 8) * 64 + (colw ^ swz)] = bf2_hi(e0, e1);
            }
        }
        __syncthreads();                               // barrier B: STS done

        // coalesced copy: 32 rows x 128B
        {
            const int row = tid >> 3;
            const int jb  = tid & 7;
            const int rsw = (row & 7) << 2;
            size_t gbase = (size_t)(row0 + row) * NN + (size_t)(c0 + i) * 128;
            #pragma unroll
            for (int hh = 0; hh < 2; hh++) {
                int blk = jb + hh * 8;
                int pos = (blk * 4) ^ rsw;
                uint4 v = *(uint4*)&sEw[i & 1][row * 64 + pos];
                *(uint4*)&g_E[gbase + blk * 8] = v;
            }
        }
    }

    rs0 += __shfl_xor_sync(0xffffffff, rs0, 1);
    rs0 += __shfl_xor_sync(0xffffffff, rs0, 2);
    rs1 += __shfl_xor_sync(0xffffffff, rs1, 1);
    rs1 += __shfl_xor_sync(0xffffffff, rs1, 2);
    if ((l & 3) == 0) {
        s_rsum[h][wm + (l >> 2)]     = rs0;
        s_rsum[h][wm + (l >> 2) + 8] = rs1;
    }
    __syncthreads();
    if (tid < 32)
        g_rowsum4[sp * NX + row0 + tid] =
            (s_rsum[0][tid] + s_rsum[1][tid]) + (s_rsum[2][tid] + s_rsum[3][tid]);
}

// =====================================================================
// K4: HMMA PV GEMM — K-split x2 (R10 config). CTA: 128 rows x 256 dout
// x half-K. 512 threads, warps 4m x 4n, warp tile 32x64.
// =====================================================================
#define PV_BK     64
#define PV_NCHS   64
#define PV_STAGEB 49152
#define PV_SMEM   (4 * PV_STAGEB + 1024)

__device__ __forceinline__ void pv_load(uint32_t tile, int tid, int row0, int gc, int c) {
    const size_t kb = (size_t)gc * (PV_BK * 2);
    const uint32_t eb = tile + (uint32_t)(c & 3) * PV_STAGEB;
    const uint32_t vb = eb + 16384u;
    #pragma unroll
    for (int p = 0; p < 2; p++) {
        int u = p * 512 + tid;
        int row = u >> 3, j = u & 7;
        CP16(eb + SW128((uint32_t)(row * 128 + j * 16)),
             (const char*)g_E + ((size_t)(row0 + row) * NN) * 2 + kb + (size_t)(j * 16));
    }
    #pragma unroll
    for (int p = 0; p < 4; p++) {
        int u = p * 512 + tid;
        int row = u >> 3, j = u & 7;
        CP16(vb + SW128((uint32_t)(row * 128 + j * 16)),
             (const char*)g_valueT + ((size_t)row * NN) * 2 + kb + (size_t)(j * 16));
    }
}

__global__ __launch_bounds__(512, 1)
void k_pv_mma() {
    extern __shared__ __align__(16) char dynsmem[];
    const int tid = threadIdx.x;
    const int wid = tid >> 5;
    const int l   = tid & 31;
    const int row0 = (int)(blockIdx.x >> 1) * 128;
    const int ks   = (int)(blockIdx.x & 1);
    const int wm0  = (wid >> 2) * 32;
    const int wn0  = (wid & 3) * 64;

    const uint32_t dynb = smem_u32(dynsmem);
    const uint32_t tile = (dynb + 1023u) & ~1023u;

    float acc[2][8][4];
    #pragma unroll
    for (int t = 0; t < 2; t++)
        #pragma unroll
        for (int u = 0; u < 8; u++)
            #pragma unroll
            for (int c = 0; c < 4; c++) acc[t][u][c] = 0.f;

    const int gc0 = ks * PV_NCHS;
    pv_load(tile, tid, row0, gc0 + 0, 0); CP_COMMIT();
    pv_load(tile, tid, row0, gc0 + 1, 1); CP_COMMIT();
    pv_load(tile, tid, row0, gc0 + 2, 2); CP_COMMIT();

    const int lm16 = l & 15;
    const int lhi  = (l >> 4) * 16;
    const int bn   = (l & 7) + ((l >> 4) << 3);
    const int bk16 = ((l >> 3) & 1) * 16;

    for (int i = 0; i < PV_NCHS; i++) {
        CP_WAIT2();
        __syncthreads();
        const uint32_t eb = tile + (uint32_t)(i & 3) * PV_STAGEB;
        const uint32_t vb = eb + 16384u;
        #pragma unroll
        for (int kk = 0; kk < 4; kk++) {
            uint32_t a[2][4];
            #pragma unroll
            for (int t = 0; t < 2; t++) {
                uint32_t off = (uint32_t)((wm0 + t * 16 + lm16) * 128 + kk * 32 + lhi);
                LDMX4(a[t][0], a[t][1], a[t][2], a[t][3], eb + SW128(off));
            }
            #pragma unroll
            for (int u2 = 0; u2 < 4; u2++) {
                uint32_t off = (uint32_t)((wn0 + u2 * 16 + bn) * 128 + kk * 32 + bk16);
                uint32_t r0, r1, r2, r3;
                LDMX4(r0, r1, r2, r3, vb + SW128(off));
                uint32_t b0[2] = {r0, r1}, b1[2] = {r2, r3};
                #pragma unroll
                for (int t = 0; t < 2; t++) {
                    MMA16816(acc[t][2 * u2],     a[t], b0);
                    MMA16816(acc[t][2 * u2 + 1], a[t], b1);
                }
            }
        }
        const int j = i + 3;
        if (j < PV_NCHS) pv_load(tile, tid, row0, gc0 + j, j);
        CP_COMMIT();
    }

    float* part = &g_pvpart[(size_t)ks * NX * DOUT];
    #pragma unroll
    for (int t = 0; t < 2; t++) {
        int ra = row0 + wm0 + t * 16 + (l >> 2);
        int rb = ra + 8;
        #pragma unroll
        for (int u = 0; u < 8; u++) {
            int col = wn0 + u * 8 + (l & 3) * 2;
            float2 v0 = {acc[t][u][0], acc[t][u][1]};
            float2 v1 = {acc[t][u][2], acc[t][u][3]};
            *(float2*)&part[(size_t)ra * DOUT + col] = v0;
            *(float2*)&part[(size_t)rb * DOUT + col] = v1;
        }
    }
}

// =====================================================================
// K5: combine PV partials + softmax normalization -> out[:, 256:512]
// =====================================================================
__global__ __launch_bounds__(256)
void k_combine(float* __restrict__ out) {
    int idx = (int)blockIdx.x * 256 + (int)threadIdx.x;
    int row = idx >> 6;
    int c4  = (idx & 63) << 2;
    float rs = 0.f;
    #pragma unroll
    for (int s = 0; s < NSPLIT; s++) rs += g_rowsum4[s * NX + row];
    float inv = 1.0f / rs;
    float4 a = *(float4*)&g_pvpart[(size_t)row * DOUT + c4];
    float4 b = *(float4*)&g_pvpart[(size_t)NX * DOUT + (size_t)row * DOUT + c4];
    float4 r = {(a.x + b.x) * inv, (a.y + b.y) * inv,
                (a.z + b.z) * inv, (a.w + b.w) * inv};
    *(float4*)&out[(size_t)row * (2 * DOUT) + DOUT + c4] = r;
}

// =====================================================================
// launch (single stream, R10 structure)
// =====================================================================
extern "C" void kernel_launch(void* const* d_in, const int* in_sizes, int n_in,
                              void* d_out, int out_size) {
    const float* x    = (const float*)d_in[0];
    const float* neigh= (const float*)d_in[1];
    const int*   adj  = (const int*)  d_in[2];
    const float* Wx1  = (const float*)d_in[3];
    const float* bx1  = (const float*)d_in[4];
    const float* Wx2  = (const float*)d_in[5];
    const float* bx2  = (const float*)d_in[6];
    const float* Wn1  = (const float*)d_in[7];
    const float* bn1  = (const float*)d_in[8];
    const float* Wn2  = (const float*)d_in[9];
    const float* bn2  = (const float*)d_in[10];
    const float* Wv   = (const float*)d_in[11];
    const float* bv   = (const float*)d_in[12];
    const float* Wfx  = (const float*)d_in[13];
    const float* bfx  = (const float*)d_in[14];
    float* out = (float*)d_out;

    __nv_bfloat16* xattb;
    __nv_bfloat16* nattb;
    cudaGetSymbolAddress((void**)&xattb, g_xattb);
    cudaGetSymbolAddress((void**)&nattb, g_nattb);

    cudaFuncSetAttribute(k_pv_mma, cudaFuncAttributeMaxDynamicSharedMemorySize, PV_SMEM);
    cudaFuncSetAttribute(k_fcx_mma, cudaFuncAttributeMaxDynamicSharedMemorySize, FC_SMEM);

    // fused attention MLPs (both branches in one grid) -> bf16 att
    k_mlp<<<2 * (NX / 128), 256>>>(neigh, Wn1, bn1, Wn2, bn2, nattb,
                                   x, Wx1, bx1, Wx2, bx2, xattb);
    // value (HMMA, transposed -> g_valueT); fc_x split-bf16 HMMA
    k_value_mma<<<128, 256>>>(neigh, Wv, bv);
    k_fcx_mma<<<128, 512, FC_SMEM>>>(x, Wfx, bfx, out);
    // HMMA scores + masked fast_exp + partial rowsums (column-split x8)
    k_score_mma<<<(NX / 32) * NSPLIT, 256>>>(adj);
    // HMMA PV (K-split x2) -> partials
    k_pv_mma<<<(NX / 128) * 2, 512, PV_SMEM>>>();
    // combine partials + softmax normalization
    k_combine<<<NX * (DOUT / 4) / 256, 256>>>(out);
}